// round 1
// baseline (speedup 1.0000x reference)
#include <cuda_runtime.h>
#include <cstdint>

#define B 16
#define N 4096
#define C 64
#define P 1024      // NPOINT
#define S 32        // NSAMPLE
#define CIN0 67
#define C1 64
#define C2 64
#define C3 128
#define CNT (B*P*S) // 524288 samples per channel for BN

#define OFF_NEWXYZ 0
#define OFF_NEWPTS (B*P*3)                 // 49152
#define OFF_IDX    (B*P*3 + B*P*C3)        // 2146304

// ---------------- scratch (static device memory; no allocations) ------------
__device__ float g_new_xyz[B*P*3];
__device__ int   g_idx[B*P*S];
__device__ float g_y1[(size_t)B*P*S*C1];   // 134 MB
__device__ float g_y2[(size_t)B*P*S*C2];   // 134 MB
__device__ float g_max3[(size_t)B*P*C3];   // 8 MB

__device__ float g_sum0[C1], g_sq0[C1], g_scale0[C1], g_shift0[C1];
__device__ float g_sum1[C2], g_sq1[C2], g_scale1[C2], g_shift1[C2];
__device__ float g_sum2[C3], g_sq2[C3], g_scale2[C3], g_shift2[C3];

// ---------------- zero stats -------------------------------------------------
__global__ void zero_stats_kernel() {
    int i = threadIdx.x;
    if (i < C1) { g_sum0[i]=0.f; g_sq0[i]=0.f; g_sum1[i]=0.f; g_sq1[i]=0.f; }
    if (i < C3) { g_sum2[i]=0.f; g_sq2[i]=0.f; }
}

// ---------------- FPS: one block per batch ----------------------------------
#define FPS_T 512
#define FPS_PP (N/FPS_T)   // 8 points per thread
__global__ void fps_kernel(const float* __restrict__ xyz, float* __restrict__ out) {
    extern __shared__ float sm[];
    float* sx = sm; float* sy = sm + N; float* sz = sm + 2*N;
    __shared__ float rv[FPS_T/32];
    __shared__ int   ri[FPS_T/32];
    __shared__ int   sfar;

    const int b = blockIdx.x;
    const int t = threadIdx.x;
    const int lane = t & 31, w = t >> 5;

    const float* base = xyz + (size_t)b * N * 3;
    for (int i = t; i < N; i += FPS_T) {
        sx[i] = base[i*3+0]; sy[i] = base[i*3+1]; sz[i] = base[i*3+2];
    }
    __syncthreads();

    float px[FPS_PP], py[FPS_PP], pz[FPS_PP], dd[FPS_PP];
    #pragma unroll
    for (int j = 0; j < FPS_PP; j++) {
        int i = t + j*FPS_T;
        px[j]=sx[i]; py[j]=sy[i]; pz[j]=sz[i]; dd[j]=1e10f;
    }

    int far = 0;
    for (int k = 0; k < P; k++) {
        float fx = sx[far], fy = sy[far], fz = sz[far];
        if (t == 0) {
            size_t gk = (size_t)b*P + k;
            g_new_xyz[gk*3+0]=fx; g_new_xyz[gk*3+1]=fy; g_new_xyz[gk*3+2]=fz;
            out[OFF_NEWXYZ + gk*3+0]=fx; out[OFF_NEWXYZ + gk*3+1]=fy; out[OFF_NEWXYZ + gk*3+2]=fz;
        }
        float bv = -1.f; int bi = 0x40000000;
        #pragma unroll
        for (int j = 0; j < FPS_PP; j++) {
            float dx = __fsub_rn(px[j], fx);
            float dy = __fsub_rn(py[j], fy);
            float dz = __fsub_rn(pz[j], fz);
            float d  = __fadd_rn(__fadd_rn(__fmul_rn(dx,dx), __fmul_rn(dy,dy)), __fmul_rn(dz,dz));
            dd[j] = fminf(dd[j], d);
            int i = t + j*FPS_T;
            if (dd[j] > bv || (dd[j] == bv && i < bi)) { bv = dd[j]; bi = i; }
        }
        #pragma unroll
        for (int off = 16; off > 0; off >>= 1) {
            float ov = __shfl_xor_sync(0xffffffffu, bv, off);
            int   oi = __shfl_xor_sync(0xffffffffu, bi, off);
            if (ov > bv || (ov == bv && oi < bi)) { bv = ov; bi = oi; }
        }
        if (lane == 0) { rv[w] = bv; ri[w] = bi; }
        __syncthreads();
        if (w == 0) {
            float v2 = (lane < FPS_T/32) ? rv[lane] : -2.f;
            int   i2 = (lane < FPS_T/32) ? ri[lane] : 0x40000000;
            #pragma unroll
            for (int off = 16; off > 0; off >>= 1) {
                float ov = __shfl_xor_sync(0xffffffffu, v2, off);
                int   oi = __shfl_xor_sync(0xffffffffu, i2, off);
                if (ov > v2 || (ov == v2 && oi < i2)) { v2 = ov; i2 = oi; }
            }
            if (lane == 0) sfar = i2;
        }
        __syncthreads();
        far = sfar;
    }
}

// ---------------- Ball query: one warp per center ---------------------------
__global__ void ballq_kernel(const float* __restrict__ xyz, float* __restrict__ out) {
    extern __shared__ float sm[];
    float* sx = sm; float* sy = sm + N; float* sz = sm + 2*N;
    const int b = blockIdx.y;
    const int tid = threadIdx.x;
    const float* base = xyz + (size_t)b * N * 3;
    for (int i = tid; i < N; i += blockDim.x) {
        sx[i] = base[i*3+0]; sy[i] = base[i*3+1]; sz[i] = base[i*3+2];
    }
    __syncthreads();

    const int w = tid >> 5, lane = tid & 31;
    const int p = blockIdx.x * 8 + w;
    const int g = b * P + p;
    const float cx = g_new_xyz[g*3+0], cy = g_new_xyz[g*3+1], cz = g_new_xyz[g*3+2];
    const float R2 = (float)(0.4 * 0.4);

    int cnt = 0, first = -1;
    for (int basei = 0; basei < N; basei += 32) {
        int i = basei + lane;
        float dx = __fsub_rn(cx, sx[i]);
        float dy = __fsub_rn(cy, sy[i]);
        float dz = __fsub_rn(cz, sz[i]);
        float d2 = __fadd_rn(__fadd_rn(__fmul_rn(dx,dx), __fmul_rn(dy,dy)), __fmul_rn(dz,dz));
        bool pred = d2 < R2;
        unsigned m = __ballot_sync(0xffffffffu, pred);
        if (first < 0 && m) first = basei + __ffs(m) - 1;
        int rank = cnt + __popc(m & ((1u << lane) - 1u));
        if (pred && rank < S) {
            g_idx[g*S + rank] = i;
            out[OFF_IDX + g*S + rank] = (float)i;
        }
        cnt += __popc(m);
        if (cnt >= S) break;
    }
    int cntc = cnt < S ? cnt : S;
    if (lane >= cntc) {
        g_idx[g*S + lane] = first;
        out[OFF_IDX + g*S + lane] = (float)first;
    }
}

// ---------------- conv1: gather + (67->64) matmul + stats -------------------
__global__ void conv1_kernel(const float* __restrict__ xyz,
                             const float* __restrict__ pts,
                             const float* __restrict__ W0) {
    __shared__ float Ws[CIN0*C1];
    const int tid = threadIdx.x;
    for (int i = tid; i < CIN0*C1; i += 256) Ws[i] = W0[i];
    __syncthreads();

    const int w = tid >> 5, lane = tid & 31;
    const int g = blockIdx.x * 8 + w;
    const int b = g >> 10;
    const int j = g_idx[g*S + lane];

    const float cx = g_new_xyz[g*3+0], cy = g_new_xyz[g*3+1], cz = g_new_xyz[g*3+2];
    const float* xr = xyz + ((size_t)b*N + j)*3;
    const float in0 = xr[0]-cx, in1 = xr[1]-cy, in2 = xr[2]-cz;

    float acc[C1];
    #pragma unroll
    for (int o = 0; o < C1; o++)
        acc[o] = fmaf(in2, Ws[2*C1+o], fmaf(in1, Ws[1*C1+o], in0*Ws[0*C1+o]));

    const float4* pr = (const float4*)(pts + ((size_t)b*N + j)*C);
    for (int q = 0; q < 16; q++) {
        float4 v = __ldg(pr + q);
        int c = 3 + q*4;
        #pragma unroll
        for (int o = 0; o < C1; o++) acc[o] = fmaf(v.x, Ws[(c+0)*C1+o], acc[o]);
        #pragma unroll
        for (int o = 0; o < C1; o++) acc[o] = fmaf(v.y, Ws[(c+1)*C1+o], acc[o]);
        #pragma unroll
        for (int o = 0; o < C1; o++) acc[o] = fmaf(v.z, Ws[(c+2)*C1+o], acc[o]);
        #pragma unroll
        for (int o = 0; o < C1; o++) acc[o] = fmaf(v.w, Ws[(c+3)*C1+o], acc[o]);
    }

    float4* yout = (float4*)(g_y1 + ((size_t)g*S + lane)*C1);
    #pragma unroll
    for (int q = 0; q < 16; q++)
        yout[q] = make_float4(acc[q*4+0], acc[q*4+1], acc[q*4+2], acc[q*4+3]);

    // stats
    float sA=0.f, qA=0.f, sB=0.f, qB=0.f;
    #pragma unroll
    for (int o = 0; o < C1; o++) {
        float s = acc[o], q2 = acc[o]*acc[o];
        #pragma unroll
        for (int off = 16; off > 0; off >>= 1) {
            s  += __shfl_xor_sync(0xffffffffu, s,  off);
            q2 += __shfl_xor_sync(0xffffffffu, q2, off);
        }
        if (lane == (o & 31)) { if (o < 32) { sA=s; qA=q2; } else { sB=s; qB=q2; } }
    }
    atomicAdd(&g_sum0[lane],     sA); atomicAdd(&g_sq0[lane],     qA);
    atomicAdd(&g_sum0[lane+32],  sB); atomicAdd(&g_sq0[lane+32],  qB);
}

// ---------------- bn params --------------------------------------------------
__global__ void bn_kernel(const float* __restrict__ gma, const float* __restrict__ bet, int layer) {
    int o = threadIdx.x;
    float *sum, *sq, *scale, *shift; int Cc;
    if (layer == 0)      { sum=g_sum0; sq=g_sq0; scale=g_scale0; shift=g_shift0; Cc=C1; }
    else if (layer == 1) { sum=g_sum1; sq=g_sq1; scale=g_scale1; shift=g_shift1; Cc=C2; }
    else                 { sum=g_sum2; sq=g_sq2; scale=g_scale2; shift=g_shift2; Cc=C3; }
    if (o >= Cc) return;
    const float inv = 1.0f / (float)CNT;
    float m = sum[o] * inv;
    float v = sq[o] * inv - m*m;
    float sc = gma[o] * rsqrtf(v + 0.001f);
    scale[o] = sc;
    shift[o] = bet[o] - m*sc;
}

// ---------------- conv2: bn0+relu on load, (64->64) matmul + stats ----------
__global__ void conv2_kernel(const float* __restrict__ W1) {
    __shared__ float Ws[C1*C2];
    __shared__ float ssc[C1], ssh[C1];
    const int tid = threadIdx.x;
    for (int i = tid; i < C1*C2; i += 256) Ws[i] = W1[i];
    if (tid < C1) { ssc[tid] = g_scale0[tid]; ssh[tid] = g_shift0[tid]; }
    __syncthreads();

    const int w = tid >> 5, lane = tid & 31;
    const int g = blockIdx.x * 8 + w;

    float acc[C2];
    #pragma unroll
    for (int o = 0; o < C2; o++) acc[o] = 0.f;

    const float4* xr = (const float4*)(g_y1 + ((size_t)g*S + lane)*C1);
    for (int q = 0; q < 16; q++) {
        float4 v = xr[q];
        int c = q*4;
        float z0 = fmaxf(fmaf(v.x, ssc[c+0], ssh[c+0]), 0.f);
        float z1 = fmaxf(fmaf(v.y, ssc[c+1], ssh[c+1]), 0.f);
        float z2 = fmaxf(fmaf(v.z, ssc[c+2], ssh[c+2]), 0.f);
        float z3 = fmaxf(fmaf(v.w, ssc[c+3], ssh[c+3]), 0.f);
        #pragma unroll
        for (int o = 0; o < C2; o++) acc[o] = fmaf(z0, Ws[(c+0)*C2+o], acc[o]);
        #pragma unroll
        for (int o = 0; o < C2; o++) acc[o] = fmaf(z1, Ws[(c+1)*C2+o], acc[o]);
        #pragma unroll
        for (int o = 0; o < C2; o++) acc[o] = fmaf(z2, Ws[(c+2)*C2+o], acc[o]);
        #pragma unroll
        for (int o = 0; o < C2; o++) acc[o] = fmaf(z3, Ws[(c+3)*C2+o], acc[o]);
    }

    float4* yout = (float4*)(g_y2 + ((size_t)g*S + lane)*C2);
    #pragma unroll
    for (int q = 0; q < 16; q++)
        yout[q] = make_float4(acc[q*4+0], acc[q*4+1], acc[q*4+2], acc[q*4+3]);

    float sA=0.f, qA=0.f, sB=0.f, qB=0.f;
    #pragma unroll
    for (int o = 0; o < C2; o++) {
        float s = acc[o], q2 = acc[o]*acc[o];
        #pragma unroll
        for (int off = 16; off > 0; off >>= 1) {
            s  += __shfl_xor_sync(0xffffffffu, s,  off);
            q2 += __shfl_xor_sync(0xffffffffu, q2, off);
        }
        if (lane == (o & 31)) { if (o < 32) { sA=s; qA=q2; } else { sB=s; qB=q2; } }
    }
    atomicAdd(&g_sum1[lane],    sA); atomicAdd(&g_sq1[lane],    qA);
    atomicAdd(&g_sum1[lane+32], sB); atomicAdd(&g_sq1[lane+32], qB);
}

// ---------------- conv3: bn1+relu on load, (64->128) matmul + stats + max ---
__global__ void conv3_kernel(const float* __restrict__ W2) {
    __shared__ float Ws[C2*C3];   // 32 KB
    __shared__ float ssc[C2], ssh[C2];
    const int tid = threadIdx.x;
    for (int i = tid; i < C2*C3; i += 256) Ws[i] = W2[i];
    if (tid < C2) { ssc[tid] = g_scale1[tid]; ssh[tid] = g_shift1[tid]; }
    __syncthreads();

    const int w = tid >> 5, lane = tid & 31;
    const int g = blockIdx.x * 8 + w;
    const float4* xr = (const float4*)(g_y2 + ((size_t)g*S + lane)*C2);

    #pragma unroll 1
    for (int h = 0; h < 2; h++) {
        float acc[64];
        #pragma unroll
        for (int o = 0; o < 64; o++) acc[o] = 0.f;

        for (int q = 0; q < 16; q++) {
            float4 v = xr[q];
            int c = q*4;
            float z0 = fmaxf(fmaf(v.x, ssc[c+0], ssh[c+0]), 0.f);
            float z1 = fmaxf(fmaf(v.y, ssc[c+1], ssh[c+1]), 0.f);
            float z2 = fmaxf(fmaf(v.z, ssc[c+2], ssh[c+2]), 0.f);
            float z3 = fmaxf(fmaf(v.w, ssc[c+3], ssh[c+3]), 0.f);
            #pragma unroll
            for (int o = 0; o < 64; o++) acc[o] = fmaf(z0, Ws[(c+0)*C3 + h*64 + o], acc[o]);
            #pragma unroll
            for (int o = 0; o < 64; o++) acc[o] = fmaf(z1, Ws[(c+1)*C3 + h*64 + o], acc[o]);
            #pragma unroll
            for (int o = 0; o < 64; o++) acc[o] = fmaf(z2, Ws[(c+2)*C3 + h*64 + o], acc[o]);
            #pragma unroll
            for (int o = 0; o < 64; o++) acc[o] = fmaf(z3, Ws[(c+3)*C3 + h*64 + o], acc[o]);
        }

        float sA=0.f, qA=0.f, mA=0.f, sB=0.f, qB=0.f, mB=0.f;
        #pragma unroll
        for (int o = 0; o < 64; o++) {
            float s = acc[o], q2 = acc[o]*acc[o], m = acc[o];
            #pragma unroll
            for (int off = 16; off > 0; off >>= 1) {
                s  += __shfl_xor_sync(0xffffffffu, s,  off);
                q2 += __shfl_xor_sync(0xffffffffu, q2, off);
                m   = fmaxf(m, __shfl_xor_sync(0xffffffffu, m, off));
            }
            if (lane == (o & 31)) { if (o < 32) { sA=s; qA=q2; mA=m; } else { sB=s; qB=q2; mB=m; } }
        }
        atomicAdd(&g_sum2[h*64+lane],    sA); atomicAdd(&g_sq2[h*64+lane],    qA);
        atomicAdd(&g_sum2[h*64+lane+32], sB); atomicAdd(&g_sq2[h*64+lane+32], qB);
        g_max3[(size_t)g*C3 + h*64 + lane]      = mA;
        g_max3[(size_t)g*C3 + h*64 + lane + 32] = mB;
    }
}

// ---------------- finalize: bn2 + relu on pooled maxes ----------------------
__global__ void finalize_kernel(float* __restrict__ out) {
    int i = blockIdx.x * blockDim.x + threadIdx.x;
    if (i < B*P*C3) {
        int o = i & 127;
        out[OFF_NEWPTS + i] = fmaxf(fmaf(g_max3[i], g_scale2[o], g_shift2[o]), 0.f);
    }
}

// ---------------- launch -----------------------------------------------------
extern "C" void kernel_launch(void* const* d_in, const int* in_sizes, int n_in,
                              void* d_out, int out_size) {
    const float* xyz = (const float*)d_in[0];
    const float* pts = (const float*)d_in[1];
    const float* W0  = (const float*)d_in[2];
    const float* g0  = (const float*)d_in[4];
    const float* be0 = (const float*)d_in[5];
    const float* W1  = (const float*)d_in[6];
    const float* g1  = (const float*)d_in[8];
    const float* be1 = (const float*)d_in[9];
    const float* W2  = (const float*)d_in[10];
    const float* g2  = (const float*)d_in[12];
    const float* be2 = (const float*)d_in[13];
    float* out = (float*)d_out;

    const int smemPts = 3 * N * (int)sizeof(float);   // 49152
    cudaFuncSetAttribute(fps_kernel,   cudaFuncAttributeMaxDynamicSharedMemorySize, smemPts);
    cudaFuncSetAttribute(ballq_kernel, cudaFuncAttributeMaxDynamicSharedMemorySize, smemPts);

    zero_stats_kernel<<<1, 128>>>();
    fps_kernel<<<B, FPS_T, smemPts>>>(xyz, out);
    ballq_kernel<<<dim3(P/8, B), 256, smemPts>>>(xyz, out);
    conv1_kernel<<<(B*P)/8, 256>>>(xyz, pts, W0);
    bn_kernel<<<1, 128>>>(g0, be0, 0);
    conv2_kernel<<<(B*P)/8, 256>>>(W1);
    bn_kernel<<<1, 128>>>(g1, be1, 1);
    conv3_kernel<<<(B*P)/8, 256>>>(W2);
    bn_kernel<<<1, 128>>>(g2, be2, 2);
    finalize_kernel<<<(B*P*C3 + 255)/256, 256>>>(out);
}

// round 2
// speedup vs baseline: 1.2169x; 1.2169x over previous
#include <cuda_runtime.h>
#include <cstdint>

#define B 16
#define N 4096
#define C 64
#define P 1024      // NPOINT
#define S 32        // NSAMPLE
#define CIN0 67
#define C1 64
#define C2 64
#define C3 128
#define CNT (B*P*S) // 524288 samples per channel for BN

#define OFF_NEWXYZ 0
#define OFF_NEWPTS (B*P*3)                 // 49152
#define OFF_IDX    (B*P*3 + B*P*C3)        // 2146304

typedef unsigned long long ull;

// ---------------- scratch (static device memory; no allocations) ------------
__device__ float g_new_xyz[B*P*3];
__device__ int   g_idx[B*P*S];
// y layout: float4 chunks: [group][chunk 0..15][lane 0..31], chunk = 4 channels
__device__ float g_y1[(size_t)B*P*S*C1];   // 134 MB
__device__ float g_y2[(size_t)B*P*S*C2];   // 134 MB
__device__ float g_max3[(size_t)B*P*C3];   // 8 MB

__device__ float g_sum0[C1], g_sq0[C1];
__device__ float g_sum1[C2], g_sq1[C2];
__device__ float g_sum2[C3], g_sq2[C3];

// ---------------- zero stats -------------------------------------------------
__global__ void zero_stats_kernel() {
    int i = threadIdx.x;
    if (i < C1) { g_sum0[i]=0.f; g_sq0[i]=0.f; g_sum1[i]=0.f; g_sq1[i]=0.f; }
    if (i < C3) { g_sum2[i]=0.f; g_sq2[i]=0.f; }
}

// ---------------- FPS: one block per batch ----------------------------------
#define FPS_T 256
#define FPS_PP (N/FPS_T)   // 16 points per thread
__global__ void fps_kernel(const float* __restrict__ xyz, float* __restrict__ out) {
    extern __shared__ float sm[];
    float* sx = sm; float* sy = sm + N; float* sz = sm + 2*N;
    __shared__ ull skey[2][FPS_T/32];

    const int b = blockIdx.x;
    const int t = threadIdx.x;
    const int lane = t & 31, w = t >> 5;

    const float* base = xyz + (size_t)b * N * 3;
    for (int i = t; i < N; i += FPS_T) {
        sx[i] = base[i*3+0]; sy[i] = base[i*3+1]; sz[i] = base[i*3+2];
    }
    __syncthreads();

    float px[FPS_PP], py[FPS_PP], pz[FPS_PP], dd[FPS_PP];
    #pragma unroll
    for (int j = 0; j < FPS_PP; j++) {
        int i = t + j*FPS_T;
        px[j]=sx[i]; py[j]=sy[i]; pz[j]=sz[i]; dd[j]=1e10f;
    }

    int far = 0;
    for (int k = 0; k < P; k++) {
        float fx = sx[far], fy = sy[far], fz = sz[far];
        if (t == 0) {
            size_t gk = (size_t)b*P + k;
            g_new_xyz[gk*3+0]=fx; g_new_xyz[gk*3+1]=fy; g_new_xyz[gk*3+2]=fz;
            out[OFF_NEWXYZ + gk*3+0]=fx; out[OFF_NEWXYZ + gk*3+1]=fy; out[OFF_NEWXYZ + gk*3+2]=fz;
        }
        // pass 1: update dists, track max value
        float bv = -1.f;
        #pragma unroll
        for (int j = 0; j < FPS_PP; j++) {
            float dx = __fsub_rn(px[j], fx);
            float dy = __fsub_rn(py[j], fy);
            float dz = __fsub_rn(pz[j], fz);
            float d  = __fadd_rn(__fadd_rn(__fmul_rn(dx,dx), __fmul_rn(dy,dy)), __fmul_rn(dz,dz));
            dd[j] = fminf(dd[j], d);
            bv = fmaxf(bv, dd[j]);
        }
        // pass 2: smallest index attaining bv
        int bi = 0x7fffffff;
        #pragma unroll
        for (int j = 0; j < FPS_PP; j++) {
            int i = t + j*FPS_T;
            if (dd[j] == bv && i < bi) bi = i;
        }
        // packed key: larger dist wins; ties -> smaller index wins
        ull key = ((ull)__float_as_uint(bv) << 32) | (unsigned)(~bi);
        #pragma unroll
        for (int off = 16; off > 0; off >>= 1) {
            ull o = __shfl_xor_sync(0xffffffffu, key, off);
            if (o > key) key = o;
        }
        if (lane == 0) skey[k & 1][w] = key;
        __syncthreads();
        ull kb = skey[k & 1][0];
        #pragma unroll
        for (int q = 1; q < FPS_T/32; q++) {
            ull o = skey[k & 1][q];
            if (o > kb) kb = o;
        }
        far = (int)(~(unsigned)kb);
    }
}

// ---------------- Ball query: one warp per center ---------------------------
__global__ void ballq_kernel(const float* __restrict__ xyz, float* __restrict__ out) {
    extern __shared__ float sm[];
    float* sx = sm; float* sy = sm + N; float* sz = sm + 2*N;
    const int b = blockIdx.y;
    const int tid = threadIdx.x;
    const float* base = xyz + (size_t)b * N * 3;
    for (int i = tid; i < N; i += blockDim.x) {
        sx[i] = base[i*3+0]; sy[i] = base[i*3+1]; sz[i] = base[i*3+2];
    }
    __syncthreads();

    const int w = tid >> 5, lane = tid & 31;
    const int p = blockIdx.x * 8 + w;
    const int g = b * P + p;
    const float cx = g_new_xyz[g*3+0], cy = g_new_xyz[g*3+1], cz = g_new_xyz[g*3+2];
    const float R2 = (float)(0.4 * 0.4);

    int cnt = 0, first = -1;
    for (int basei = 0; basei < N; basei += 32) {
        int i = basei + lane;
        float dx = __fsub_rn(cx, sx[i]);
        float dy = __fsub_rn(cy, sy[i]);
        float dz = __fsub_rn(cz, sz[i]);
        float d2 = __fadd_rn(__fadd_rn(__fmul_rn(dx,dx), __fmul_rn(dy,dy)), __fmul_rn(dz,dz));
        bool pred = d2 < R2;
        unsigned m = __ballot_sync(0xffffffffu, pred);
        if (first < 0 && m) first = basei + __ffs(m) - 1;
        int rank = cnt + __popc(m & ((1u << lane) - 1u));
        if (pred && rank < S) {
            g_idx[g*S + rank] = i;
            out[OFF_IDX + g*S + rank] = (float)i;
        }
        cnt += __popc(m);
        if (cnt >= S) break;
    }
    int cntc = cnt < S ? cnt : S;
    if (lane >= cntc) {
        g_idx[g*S + lane] = first;
        out[OFF_IDX + g*S + lane] = (float)first;
    }
}

// ---------------- conv1: gather + (67->64), 2 warps/group -------------------
__global__ __launch_bounds__(256, 3) void conv1_kernel(const float* __restrict__ xyz,
                                                       const float* __restrict__ pts,
                                                       const float* __restrict__ W0) {
    __shared__ float Ws[CIN0*C1];           // 17152 B
    const int tid = threadIdx.x;
    for (int i = tid; i < CIN0*C1; i += 256) Ws[i] = W0[i];
    __syncthreads();

    const int w = tid >> 5, lane = tid & 31;
    const int g = blockIdx.x * 4 + (w >> 1);
    const int half = w & 1, ob = half * 32;
    const int b = g >> 10;
    const int j = g_idx[g*S + lane];

    const float cx = g_new_xyz[g*3+0], cy = g_new_xyz[g*3+1], cz = g_new_xyz[g*3+2];
    const float* xr = xyz + ((size_t)b*N + j)*3;
    const float in0 = xr[0]-cx, in1 = xr[1]-cy, in2 = xr[2]-cz;

    float acc[32];
    #pragma unroll
    for (int o = 0; o < 32; o++)
        acc[o] = fmaf(in2, Ws[2*C1+ob+o], fmaf(in1, Ws[1*C1+ob+o], in0*Ws[ob+o]));

    const float4* pr = (const float4*)(pts + ((size_t)b*N + j)*C);
    #pragma unroll 4
    for (int q = 0; q < 16; q++) {
        float4 v = __ldg(pr + q);
        int c = 3 + q*4;
        #pragma unroll
        for (int o = 0; o < 32; o++) acc[o] = fmaf(v.x, Ws[(c+0)*C1+ob+o], acc[o]);
        #pragma unroll
        for (int o = 0; o < 32; o++) acc[o] = fmaf(v.y, Ws[(c+1)*C1+ob+o], acc[o]);
        #pragma unroll
        for (int o = 0; o < 32; o++) acc[o] = fmaf(v.z, Ws[(c+2)*C1+ob+o], acc[o]);
        #pragma unroll
        for (int o = 0; o < 32; o++) acc[o] = fmaf(v.w, Ws[(c+3)*C1+ob+o], acc[o]);
    }

    // coalesced store: chunk = 4 channels, lanes contiguous
    float4* y4 = (float4*)g_y1;
    #pragma unroll
    for (int q = 0; q < 8; q++)
        y4[((size_t)g*16 + half*8 + q)*32 + lane] =
            make_float4(acc[q*4+0], acc[q*4+1], acc[q*4+2], acc[q*4+3]);

    float sA=0.f, qA=0.f;
    #pragma unroll
    for (int o = 0; o < 32; o++) {
        float s = acc[o], q2 = acc[o]*acc[o];
        #pragma unroll
        for (int off = 16; off > 0; off >>= 1) {
            s  += __shfl_xor_sync(0xffffffffu, s,  off);
            q2 += __shfl_xor_sync(0xffffffffu, q2, off);
        }
        if (lane == o) { sA = s; qA = q2; }
    }
    atomicAdd(&g_sum0[ob+lane], sA);
    atomicAdd(&g_sq0[ob+lane],  qA);
}

// ---------------- conv2: bn0+relu on load, (64->64), 2 warps/group ----------
__global__ __launch_bounds__(256, 3) void conv2_kernel(const float* __restrict__ W1,
                                                       const float* __restrict__ g0,
                                                       const float* __restrict__ be0) {
    __shared__ float Ws[C1*C2];             // 16 KB
    __shared__ float ssc[C1], ssh[C1];
    const int tid = threadIdx.x;
    for (int i = tid; i < C1*C2; i += 256) Ws[i] = W1[i];
    if (tid < C1) {
        const float inv = 1.0f / (float)CNT;
        float m = g_sum0[tid] * inv;
        float v = g_sq0[tid] * inv - m*m;
        float sc = g0[tid] * rsqrtf(v + 0.001f);
        ssc[tid] = sc; ssh[tid] = be0[tid] - m*sc;
    }
    __syncthreads();

    const int w = tid >> 5, lane = tid & 31;
    const int g = blockIdx.x * 4 + (w >> 1);
    const int half = w & 1, ob = half * 32;

    float acc[32];
    #pragma unroll
    for (int o = 0; o < 32; o++) acc[o] = 0.f;

    const float4* x4 = (const float4*)g_y1 + (size_t)g*512 + lane;
    #pragma unroll 4
    for (int q = 0; q < 16; q++) {
        float4 v = x4[q*32];
        int c = q*4;
        float z0 = fmaxf(fmaf(v.x, ssc[c+0], ssh[c+0]), 0.f);
        float z1 = fmaxf(fmaf(v.y, ssc[c+1], ssh[c+1]), 0.f);
        float z2 = fmaxf(fmaf(v.z, ssc[c+2], ssh[c+2]), 0.f);
        float z3 = fmaxf(fmaf(v.w, ssc[c+3], ssh[c+3]), 0.f);
        #pragma unroll
        for (int o = 0; o < 32; o++) acc[o] = fmaf(z0, Ws[(c+0)*C2+ob+o], acc[o]);
        #pragma unroll
        for (int o = 0; o < 32; o++) acc[o] = fmaf(z1, Ws[(c+1)*C2+ob+o], acc[o]);
        #pragma unroll
        for (int o = 0; o < 32; o++) acc[o] = fmaf(z2, Ws[(c+2)*C2+ob+o], acc[o]);
        #pragma unroll
        for (int o = 0; o < 32; o++) acc[o] = fmaf(z3, Ws[(c+3)*C2+ob+o], acc[o]);
    }

    float4* y4 = (float4*)g_y2;
    #pragma unroll
    for (int q = 0; q < 8; q++)
        y4[((size_t)g*16 + half*8 + q)*32 + lane] =
            make_float4(acc[q*4+0], acc[q*4+1], acc[q*4+2], acc[q*4+3]);

    float sA=0.f, qA=0.f;
    #pragma unroll
    for (int o = 0; o < 32; o++) {
        float s = acc[o], q2 = acc[o]*acc[o];
        #pragma unroll
        for (int off = 16; off > 0; off >>= 1) {
            s  += __shfl_xor_sync(0xffffffffu, s,  off);
            q2 += __shfl_xor_sync(0xffffffffu, q2, off);
        }
        if (lane == o) { sA = s; qA = q2; }
    }
    atomicAdd(&g_sum1[ob+lane], sA);
    atomicAdd(&g_sq1[ob+lane],  qA);
}

// ---------------- conv3: bn1+relu on load, (64->128), 4 warps/group + max ---
__global__ __launch_bounds__(256, 3) void conv3_kernel(const float* __restrict__ W2,
                                                       const float* __restrict__ g1,
                                                       const float* __restrict__ be1) {
    __shared__ float Ws[C2*C3];             // 32 KB
    __shared__ float ssc[C2], ssh[C2];
    const int tid = threadIdx.x;
    for (int i = tid; i < C2*C3; i += 256) Ws[i] = W2[i];
    if (tid < C2) {
        const float inv = 1.0f / (float)CNT;
        float m = g_sum1[tid] * inv;
        float v = g_sq1[tid] * inv - m*m;
        float sc = g1[tid] * rsqrtf(v + 0.001f);
        ssc[tid] = sc; ssh[tid] = be1[tid] - m*sc;
    }
    __syncthreads();

    const int w = tid >> 5, lane = tid & 31;
    const int g = blockIdx.x * 2 + (w >> 2);
    const int qtr = w & 3, ob = qtr * 32;

    float acc[32];
    #pragma unroll
    for (int o = 0; o < 32; o++) acc[o] = 0.f;

    const float4* x4 = (const float4*)g_y2 + (size_t)g*512 + lane;
    #pragma unroll 4
    for (int q = 0; q < 16; q++) {
        float4 v = x4[q*32];
        int c = q*4;
        float z0 = fmaxf(fmaf(v.x, ssc[c+0], ssh[c+0]), 0.f);
        float z1 = fmaxf(fmaf(v.y, ssc[c+1], ssh[c+1]), 0.f);
        float z2 = fmaxf(fmaf(v.z, ssc[c+2], ssh[c+2]), 0.f);
        float z3 = fmaxf(fmaf(v.w, ssc[c+3], ssh[c+3]), 0.f);
        #pragma unroll
        for (int o = 0; o < 32; o++) acc[o] = fmaf(z0, Ws[(c+0)*C3+ob+o], acc[o]);
        #pragma unroll
        for (int o = 0; o < 32; o++) acc[o] = fmaf(z1, Ws[(c+1)*C3+ob+o], acc[o]);
        #pragma unroll
        for (int o = 0; o < 32; o++) acc[o] = fmaf(z2, Ws[(c+2)*C3+ob+o], acc[o]);
        #pragma unroll
        for (int o = 0; o < 32; o++) acc[o] = fmaf(z3, Ws[(c+3)*C3+ob+o], acc[o]);
    }

    float sA=0.f, qA=0.f, mA=0.f;
    #pragma unroll
    for (int o = 0; o < 32; o++) {
        float s = acc[o], q2 = acc[o]*acc[o], m = acc[o];
        #pragma unroll
        for (int off = 16; off > 0; off >>= 1) {
            s  += __shfl_xor_sync(0xffffffffu, s,  off);
            q2 += __shfl_xor_sync(0xffffffffu, q2, off);
            m   = fmaxf(m, __shfl_xor_sync(0xffffffffu, m, off));
        }
        if (lane == o) { sA = s; qA = q2; mA = m; }
    }
    atomicAdd(&g_sum2[ob+lane], sA);
    atomicAdd(&g_sq2[ob+lane],  qA);
    g_max3[(size_t)g*C3 + ob + lane] = mA;
}

// ---------------- finalize: bn2 + relu on pooled maxes ----------------------
__global__ void finalize_kernel(const float* __restrict__ g2,
                                const float* __restrict__ be2,
                                float* __restrict__ out) {
    __shared__ float sc[C3], sh[C3];
    const int tid = threadIdx.x;
    if (tid < C3) {
        const float inv = 1.0f / (float)CNT;
        float m = g_sum2[tid] * inv;
        float v = g_sq2[tid] * inv - m*m;
        float s = g2[tid] * rsqrtf(v + 0.001f);
        sc[tid] = s; sh[tid] = be2[tid] - m*s;
    }
    __syncthreads();
    for (int i = blockIdx.x * blockDim.x + tid; i < B*P*C3; i += gridDim.x * blockDim.x) {
        int o = i & 127;
        out[OFF_NEWPTS + i] = fmaxf(fmaf(g_max3[i], sc[o], sh[o]), 0.f);
    }
}

// ---------------- launch -----------------------------------------------------
extern "C" void kernel_launch(void* const* d_in, const int* in_sizes, int n_in,
                              void* d_out, int out_size) {
    const float* xyz = (const float*)d_in[0];
    const float* pts = (const float*)d_in[1];
    const float* W0  = (const float*)d_in[2];
    const float* g0  = (const float*)d_in[4];
    const float* be0 = (const float*)d_in[5];
    const float* W1  = (const float*)d_in[6];
    const float* g1  = (const float*)d_in[8];
    const float* be1 = (const float*)d_in[9];
    const float* W2  = (const float*)d_in[10];
    const float* g2  = (const float*)d_in[12];
    const float* be2 = (const float*)d_in[13];
    float* out = (float*)d_out;

    const int smemPts = 3 * N * (int)sizeof(float);   // 49152
    cudaFuncSetAttribute(fps_kernel,   cudaFuncAttributeMaxDynamicSharedMemorySize, smemPts);
    cudaFuncSetAttribute(ballq_kernel, cudaFuncAttributeMaxDynamicSharedMemorySize, smemPts);

    zero_stats_kernel<<<1, 128>>>();
    fps_kernel<<<B, FPS_T, smemPts>>>(xyz, out);
    ballq_kernel<<<dim3(P/8, B), 256, smemPts>>>(xyz, out);
    conv1_kernel<<<(B*P)/4, 256>>>(xyz, pts, W0);
    conv2_kernel<<<(B*P)/4, 256>>>(W1, g0, be0);
    conv3_kernel<<<(B*P)/2, 256>>>(W2, g1, be1);
    finalize_kernel<<<2048, 256>>>(g2, be2, out);
}

// round 3
// speedup vs baseline: 1.6718x; 1.3739x over previous
#include <cuda_runtime.h>
#include <cstdint>

#define B 16
#define N 4096
#define C 64
#define P 1024      // NPOINT
#define S 32        // NSAMPLE
#define CIN0 67
#define C1 64
#define C2 64
#define C3 128
#define CNT (B*P*S) // 524288 samples per channel for BN

#define OFF_NEWXYZ 0
#define OFF_NEWPTS (B*P*3)                 // 49152
#define OFF_IDX    (B*P*3 + B*P*C3)        // 2146304

typedef unsigned long long ull;

// ---------------- f32x2 packed helpers (sm_103a) -----------------------------
__device__ __forceinline__ ull pk2(float x) {
    ull r; asm("mov.b64 %0, {%1, %1};" : "=l"(r) : "f"(x)); return r;
}
__device__ __forceinline__ ull fma2(ull a, ull b, ull c) {
    ull d; asm("fma.rn.f32x2 %0, %1, %2, %3;" : "=l"(d) : "l"(a), "l"(b), "l"(c)); return d;
}
__device__ __forceinline__ ull mul2(ull a, ull b) {
    ull d; asm("mul.rn.f32x2 %0, %1, %2;" : "=l"(d) : "l"(a), "l"(b)); return d;
}
__device__ __forceinline__ ull add2(ull a, ull b) {
    ull d; asm("add.rn.f32x2 %0, %1, %2;" : "=l"(d) : "l"(a), "l"(b)); return d;
}
__device__ __forceinline__ void upk(ull a, float& lo, float& hi) {
    asm("mov.b64 {%0, %1}, %2;" : "=f"(lo), "=f"(hi) : "l"(a));
}
__device__ __forceinline__ ull shfl64(ull v, int off) {
    return __shfl_xor_sync(0xffffffffu, v, off);
}

// ---------------- scratch (static device memory; no allocations) ------------
__device__ float g_new_xyz[B*P*3];
__device__ int   g_idx[B*P*S];
// y layout: 16B chunks: [group][chunk 0..15][lane 0..31], chunk = 4 channels
__device__ float g_y1[(size_t)B*P*S*C1];   // 134 MB
__device__ float g_y2[(size_t)B*P*S*C2];   // 134 MB
__device__ float g_max3[(size_t)B*P*C3];   // 8 MB

__device__ float g_sum0[C1], g_sq0[C1];
__device__ float g_sum1[C2], g_sq1[C2];
__device__ float g_sum2[C3], g_sq2[C3];

// ---------------- zero stats -------------------------------------------------
__global__ void zero_stats_kernel() {
    int i = threadIdx.x;
    if (i < C1) { g_sum0[i]=0.f; g_sq0[i]=0.f; g_sum1[i]=0.f; g_sq1[i]=0.f; }
    if (i < C3) { g_sum2[i]=0.f; g_sq2[i]=0.f; }
}

// ---------------- FPS: one block per batch ----------------------------------
#define FPS_T 256
#define FPS_PP (N/FPS_T)   // 16 points per thread
__global__ void fps_kernel(const float* __restrict__ xyz, float* __restrict__ out) {
    extern __shared__ float sm[];
    float* sx = sm; float* sy = sm + N; float* sz = sm + 2*N;
    __shared__ ull skey[2][FPS_T/32];

    const int b = blockIdx.x;
    const int t = threadIdx.x;
    const int lane = t & 31, w = t >> 5;

    const float* base = xyz + (size_t)b * N * 3;
    for (int i = t; i < N; i += FPS_T) {
        sx[i] = base[i*3+0]; sy[i] = base[i*3+1]; sz[i] = base[i*3+2];
    }
    __syncthreads();

    float px[FPS_PP], py[FPS_PP], pz[FPS_PP], dd[FPS_PP];
    #pragma unroll
    for (int j = 0; j < FPS_PP; j++) {
        int i = t + j*FPS_T;
        px[j]=sx[i]; py[j]=sy[i]; pz[j]=sz[i]; dd[j]=1e10f;
    }

    int far = 0;
    for (int k = 0; k < P; k++) {
        float fx = sx[far], fy = sy[far], fz = sz[far];
        if (t == 0) {
            size_t gk = (size_t)b*P + k;
            g_new_xyz[gk*3+0]=fx; g_new_xyz[gk*3+1]=fy; g_new_xyz[gk*3+2]=fz;
            out[OFF_NEWXYZ + gk*3+0]=fx; out[OFF_NEWXYZ + gk*3+1]=fy; out[OFF_NEWXYZ + gk*3+2]=fz;
        }
        // fused update + local argmax (strict > keeps smallest index on ties,
        // since i is ascending within the thread and threads interleave by t)
        float bv = -1.f; int bi = 0x7fffffff;
        #pragma unroll
        for (int j = 0; j < FPS_PP; j++) {
            float dx = __fsub_rn(px[j], fx);
            float dy = __fsub_rn(py[j], fy);
            float dz = __fsub_rn(pz[j], fz);
            float d  = __fadd_rn(__fadd_rn(__fmul_rn(dx,dx), __fmul_rn(dy,dy)), __fmul_rn(dz,dz));
            dd[j] = fminf(dd[j], d);
            if (dd[j] > bv) { bv = dd[j]; bi = t + j*FPS_T; }
        }
        // warp reduce: max dist (bits monotonic, dd>=0), then min index among winners
        unsigned bvb = __float_as_uint(bv);
        unsigned mb  = __reduce_max_sync(0xffffffffu, bvb);
        unsigned bim = (bvb == mb) ? (unsigned)bi : 0x7fffffffu;
        unsigned bmin = __reduce_min_sync(0xffffffffu, bim);
        if (lane == 0) skey[k & 1][w] = ((ull)mb << 32) | (unsigned)(~bmin);
        __syncthreads();
        ull kb = skey[k & 1][0];
        #pragma unroll
        for (int q = 1; q < FPS_T/32; q++) {
            ull o = skey[k & 1][q];
            if (o > kb) kb = o;
        }
        far = (int)(~(unsigned)kb);
    }
}

// ---------------- Ball query: one warp per center ---------------------------
__global__ void ballq_kernel(const float* __restrict__ xyz, float* __restrict__ out) {
    extern __shared__ float sm[];
    float* sx = sm; float* sy = sm + N; float* sz = sm + 2*N;
    const int b = blockIdx.y;
    const int tid = threadIdx.x;
    const float* base = xyz + (size_t)b * N * 3;
    for (int i = tid; i < N; i += blockDim.x) {
        sx[i] = base[i*3+0]; sy[i] = base[i*3+1]; sz[i] = base[i*3+2];
    }
    __syncthreads();

    const int w = tid >> 5, lane = tid & 31;
    const int p = blockIdx.x * 8 + w;
    const int g = b * P + p;
    const float cx = g_new_xyz[g*3+0], cy = g_new_xyz[g*3+1], cz = g_new_xyz[g*3+2];
    const float R2 = (float)(0.4 * 0.4);

    int cnt = 0, first = -1;
    for (int basei = 0; basei < N; basei += 32) {
        int i = basei + lane;
        float dx = __fsub_rn(cx, sx[i]);
        float dy = __fsub_rn(cy, sy[i]);
        float dz = __fsub_rn(cz, sz[i]);
        float d2 = __fadd_rn(__fadd_rn(__fmul_rn(dx,dx), __fmul_rn(dy,dy)), __fmul_rn(dz,dz));
        bool pred = d2 < R2;
        unsigned m = __ballot_sync(0xffffffffu, pred);
        if (first < 0 && m) first = basei + __ffs(m) - 1;
        int rank = cnt + __popc(m & ((1u << lane) - 1u));
        if (pred && rank < S) {
            g_idx[g*S + rank] = i;
            out[OFF_IDX + g*S + rank] = (float)i;
        }
        cnt += __popc(m);
        if (cnt >= S) break;
    }
    int cntc = cnt < S ? cnt : S;
    if (lane >= cntc) {
        g_idx[g*S + lane] = first;
        out[OFF_IDX + g*S + lane] = (float)first;
    }
}

// =============================================================================
// Convs: warp = (group pair) x (16 output channels). Lane holds sample `lane`
// of group g0 AND of group g1. Weights loaded once per input channel serve
// both samples: 4x LDS.128 -> 16x fma.rn.f32x2.
// =============================================================================

// ---------------- conv1: gather + (67->64) -----------------------------------
__global__ __launch_bounds__(256, 3) void conv1_kernel(const float* __restrict__ xyz,
                                                       const float* __restrict__ pts,
                                                       const float* __restrict__ W0) {
    __shared__ __align__(16) float Ws[CIN0*C1];           // 17152 B
    const int tid = threadIdx.x;
    for (int i = tid; i < CIN0*C1; i += 256) Ws[i] = W0[i];
    __syncthreads();

    const int w = tid >> 5, lane = tid & 31;
    const int gp = blockIdx.x * 2 + (w >> 2);
    const int quarter = w & 3, ob = quarter * 16;
    const int g0 = gp*2, g1 = gp*2+1;
    const int b = g0 >> 10;

    const int ja = g_idx[g0*S + lane];
    const int jb = g_idx[g1*S + lane];

    const float* xra = xyz + ((size_t)b*N + ja)*3;
    const float* xrb = xyz + ((size_t)b*N + jb)*3;
    float ia[3], ib[3];
    ia[0] = xra[0] - g_new_xyz[g0*3+0]; ia[1] = xra[1] - g_new_xyz[g0*3+1]; ia[2] = xra[2] - g_new_xyz[g0*3+2];
    ib[0] = xrb[0] - g_new_xyz[g1*3+0]; ib[1] = xrb[1] - g_new_xyz[g1*3+1]; ib[2] = xrb[2] - g_new_xyz[g1*3+2];

    ull acca[8], accb[8];
    {   // c = 0 initializes, c = 1,2 accumulate
        ull za = pk2(ia[0]), zb = pk2(ib[0]);
        const ulonglong2* wr = (const ulonglong2*)(Ws + 0*C1 + ob);
        #pragma unroll
        for (int p2 = 0; p2 < 4; p2++) {
            ulonglong2 wv = wr[p2];
            acca[2*p2]   = mul2(za, wv.x); acca[2*p2+1] = mul2(za, wv.y);
            accb[2*p2]   = mul2(zb, wv.x); accb[2*p2+1] = mul2(zb, wv.y);
        }
        #pragma unroll
        for (int c = 1; c < 3; c++) {
            ull za2 = pk2(ia[c]), zb2 = pk2(ib[c]);
            const ulonglong2* wr2 = (const ulonglong2*)(Ws + c*C1 + ob);
            #pragma unroll
            for (int p2 = 0; p2 < 4; p2++) {
                ulonglong2 wv = wr2[p2];
                acca[2*p2]   = fma2(za2, wv.x, acca[2*p2]);   acca[2*p2+1] = fma2(za2, wv.y, acca[2*p2+1]);
                accb[2*p2]   = fma2(zb2, wv.x, accb[2*p2]);   accb[2*p2+1] = fma2(zb2, wv.y, accb[2*p2+1]);
            }
        }
    }

    const float4* pra = (const float4*)(pts + ((size_t)b*N + ja)*C);
    const float4* prb = (const float4*)(pts + ((size_t)b*N + jb)*C);
    #pragma unroll 4
    for (int q = 0; q < 16; q++) {
        float4 va = __ldg(pra + q);
        float4 vb = __ldg(prb + q);
        int c = 3 + q*4;
        float fa[4] = {va.x, va.y, va.z, va.w};
        float fb[4] = {vb.x, vb.y, vb.z, vb.w};
        #pragma unroll
        for (int u = 0; u < 4; u++) {
            ull za = pk2(fa[u]), zb = pk2(fb[u]);
            const ulonglong2* wr = (const ulonglong2*)(Ws + (c+u)*C1 + ob);
            #pragma unroll
            for (int p2 = 0; p2 < 4; p2++) {
                ulonglong2 wv = wr[p2];
                acca[2*p2]   = fma2(za, wv.x, acca[2*p2]);   acca[2*p2+1] = fma2(za, wv.y, acca[2*p2+1]);
                accb[2*p2]   = fma2(zb, wv.x, accb[2*p2]);   accb[2*p2+1] = fma2(zb, wv.y, accb[2*p2+1]);
            }
        }
    }

    // stores: chunks quarter*4 .. quarter*4+3 (each chunk = 4 ch = 1 ulonglong2)
    ulonglong2* yv = (ulonglong2*)g_y1;
    #pragma unroll
    for (int t2 = 0; t2 < 4; t2++) {
        ulonglong2 va, vb;
        va.x = acca[2*t2]; va.y = acca[2*t2+1];
        vb.x = accb[2*t2]; vb.y = accb[2*t2+1];
        yv[((size_t)g0*16 + quarter*4 + t2)*32 + lane] = va;
        yv[((size_t)g1*16 + quarter*4 + t2)*32 + lane] = vb;
    }

    // stats (pairwise f32x2)
    ull ssum = 0, ssq = 0;
    #pragma unroll
    for (int p2 = 0; p2 < 8; p2++) {
        ull s  = add2(acca[p2], accb[p2]);
        ull q2 = add2(mul2(acca[p2], acca[p2]), mul2(accb[p2], accb[p2]));
        #pragma unroll
        for (int off = 16; off > 0; off >>= 1) {
            s  = add2(s,  shfl64(s,  off));
            q2 = add2(q2, shfl64(q2, off));
        }
        if (lane == p2) { ssum = s; ssq = q2; }
    }
    if (lane < 8) {
        float slo, shi, qlo, qhi;
        upk(ssum, slo, shi); upk(ssq, qlo, qhi);
        atomicAdd(&g_sum0[ob + 2*lane],     slo);
        atomicAdd(&g_sum0[ob + 2*lane + 1], shi);
        atomicAdd(&g_sq0[ob + 2*lane],      qlo);
        atomicAdd(&g_sq0[ob + 2*lane + 1],  qhi);
    }
}

// ---------------- conv2: bn0+relu on load, (64->64) --------------------------
__global__ __launch_bounds__(256, 3) void conv2_kernel(const float* __restrict__ W1,
                                                       const float* __restrict__ g0p,
                                                       const float* __restrict__ be0) {
    __shared__ __align__(16) float Ws[C1*C2];             // 16 KB
    __shared__ float ssc[C1], ssh[C1];
    const int tid = threadIdx.x;
    for (int i = tid; i < C1*C2; i += 256) Ws[i] = W1[i];
    if (tid < C1) {
        const float inv = 1.0f / (float)CNT;
        float m = g_sum0[tid] * inv;
        float v = g_sq0[tid] * inv - m*m;
        float sc = g0p[tid] * rsqrtf(v + 0.001f);
        ssc[tid] = sc; ssh[tid] = be0[tid] - m*sc;
    }
    __syncthreads();

    const int w = tid >> 5, lane = tid & 31;
    const int gp = blockIdx.x * 2 + (w >> 2);
    const int quarter = w & 3, ob = quarter * 16;
    const int g0 = gp*2, g1 = gp*2+1;

    ull acca[8], accb[8];
    #pragma unroll
    for (int p2 = 0; p2 < 8; p2++) { acca[p2] = 0ull; accb[p2] = 0ull; }

    const float4* xa = (const float4*)g_y1 + (size_t)g0*512 + lane;
    const float4* xb = (const float4*)g_y1 + (size_t)g1*512 + lane;
    #pragma unroll 4
    for (int q = 0; q < 16; q++) {
        float4 va = xa[q*32];
        float4 vb = xb[q*32];
        int c = q*4;
        float fa[4] = {va.x, va.y, va.z, va.w};
        float fb[4] = {vb.x, vb.y, vb.z, vb.w};
        #pragma unroll
        for (int u = 0; u < 4; u++) {
            float za = fmaxf(fmaf(fa[u], ssc[c+u], ssh[c+u]), 0.f);
            float zb = fmaxf(fmaf(fb[u], ssc[c+u], ssh[c+u]), 0.f);
            ull zza = pk2(za), zzb = pk2(zb);
            const ulonglong2* wr = (const ulonglong2*)(Ws + (c+u)*C2 + ob);
            #pragma unroll
            for (int p2 = 0; p2 < 4; p2++) {
                ulonglong2 wv = wr[p2];
                acca[2*p2]   = fma2(zza, wv.x, acca[2*p2]);   acca[2*p2+1] = fma2(zza, wv.y, acca[2*p2+1]);
                accb[2*p2]   = fma2(zzb, wv.x, accb[2*p2]);   accb[2*p2+1] = fma2(zzb, wv.y, accb[2*p2+1]);
            }
        }
    }

    ulonglong2* yv = (ulonglong2*)g_y2;
    #pragma unroll
    for (int t2 = 0; t2 < 4; t2++) {
        ulonglong2 va, vb;
        va.x = acca[2*t2]; va.y = acca[2*t2+1];
        vb.x = accb[2*t2]; vb.y = accb[2*t2+1];
        yv[((size_t)g0*16 + quarter*4 + t2)*32 + lane] = va;
        yv[((size_t)g1*16 + quarter*4 + t2)*32 + lane] = vb;
    }

    ull ssum = 0, ssq = 0;
    #pragma unroll
    for (int p2 = 0; p2 < 8; p2++) {
        ull s  = add2(acca[p2], accb[p2]);
        ull q2 = add2(mul2(acca[p2], acca[p2]), mul2(accb[p2], accb[p2]));
        #pragma unroll
        for (int off = 16; off > 0; off >>= 1) {
            s  = add2(s,  shfl64(s,  off));
            q2 = add2(q2, shfl64(q2, off));
        }
        if (lane == p2) { ssum = s; ssq = q2; }
    }
    if (lane < 8) {
        float slo, shi, qlo, qhi;
        upk(ssum, slo, shi); upk(ssq, qlo, qhi);
        atomicAdd(&g_sum1[ob + 2*lane],     slo);
        atomicAdd(&g_sum1[ob + 2*lane + 1], shi);
        atomicAdd(&g_sq1[ob + 2*lane],      qlo);
        atomicAdd(&g_sq1[ob + 2*lane + 1],  qhi);
    }
}

// ---------------- conv3: bn1+relu on load, (64->128) + max-pool --------------
__global__ __launch_bounds__(256, 3) void conv3_kernel(const float* __restrict__ W2,
                                                       const float* __restrict__ g1p,
                                                       const float* __restrict__ be1) {
    __shared__ __align__(16) float Ws[C2*C3];             // 32 KB
    __shared__ float ssc[C2], ssh[C2];
    const int tid = threadIdx.x;
    for (int i = tid; i < C2*C3; i += 256) Ws[i] = W2[i];
    if (tid < C2) {
        const float inv = 1.0f / (float)CNT;
        float m = g_sum1[tid] * inv;
        float v = g_sq1[tid] * inv - m*m;
        float sc = g1p[tid] * rsqrtf(v + 0.001f);
        ssc[tid] = sc; ssh[tid] = be1[tid] - m*sc;
    }
    __syncthreads();

    const int w = tid >> 5, lane = tid & 31;
    const int gp = blockIdx.x;
    const int ob = w * 16;          // 8 warps x 16 channels = 128
    const int g0 = gp*2, g1 = gp*2+1;

    ull acca[8], accb[8];
    #pragma unroll
    for (int p2 = 0; p2 < 8; p2++) { acca[p2] = 0ull; accb[p2] = 0ull; }

    const float4* xa = (const float4*)g_y2 + (size_t)g0*512 + lane;
    const float4* xb = (const float4*)g_y2 + (size_t)g1*512 + lane;
    #pragma unroll 4
    for (int q = 0; q < 16; q++) {
        float4 va = xa[q*32];
        float4 vb = xb[q*32];
        int c = q*4;
        float fa[4] = {va.x, va.y, va.z, va.w};
        float fb[4] = {vb.x, vb.y, vb.z, vb.w};
        #pragma unroll
        for (int u = 0; u < 4; u++) {
            float za = fmaxf(fmaf(fa[u], ssc[c+u], ssh[c+u]), 0.f);
            float zb = fmaxf(fmaf(fb[u], ssc[c+u], ssh[c+u]), 0.f);
            ull zza = pk2(za), zzb = pk2(zb);
            const ulonglong2* wr = (const ulonglong2*)(Ws + (c+u)*C3 + ob);
            #pragma unroll
            for (int p2 = 0; p2 < 4; p2++) {
                ulonglong2 wv = wr[p2];
                acca[2*p2]   = fma2(zza, wv.x, acca[2*p2]);   acca[2*p2+1] = fma2(zza, wv.y, acca[2*p2+1]);
                accb[2*p2]   = fma2(zzb, wv.x, accb[2*p2]);   accb[2*p2+1] = fma2(zzb, wv.y, accb[2*p2+1]);
            }
        }
    }

    // stats
    ull ssum = 0, ssq = 0;
    #pragma unroll
    for (int p2 = 0; p2 < 8; p2++) {
        ull s  = add2(acca[p2], accb[p2]);
        ull q2 = add2(mul2(acca[p2], acca[p2]), mul2(accb[p2], accb[p2]));
        #pragma unroll
        for (int off = 16; off > 0; off >>= 1) {
            s  = add2(s,  shfl64(s,  off));
            q2 = add2(q2, shfl64(q2, off));
        }
        if (lane == p2) { ssum = s; ssq = q2; }
    }
    if (lane < 8) {
        float slo, shi, qlo, qhi;
        upk(ssum, slo, shi); upk(ssq, qlo, qhi);
        atomicAdd(&g_sum2[ob + 2*lane],     slo);
        atomicAdd(&g_sum2[ob + 2*lane + 1], shi);
        atomicAdd(&g_sq2[ob + 2*lane],      qlo);
        atomicAdd(&g_sq2[ob + 2*lane + 1],  qhi);
    }

    // max over samples (scalar butterflies per channel)
    float resA = 0.f, resB = 0.f;
    #pragma unroll
    for (int i = 0; i < 16; i++) {
        float la, ha, lb, hb;
        upk(acca[i>>1], la, ha);
        upk(accb[i>>1], lb, hb);
        float ra = (i & 1) ? ha : la;
        float rb = (i & 1) ? hb : lb;
        #pragma unroll
        for (int off = 16; off > 0; off >>= 1) {
            ra = fmaxf(ra, __shfl_xor_sync(0xffffffffu, ra, off));
            rb = fmaxf(rb, __shfl_xor_sync(0xffffffffu, rb, off));
        }
        if (lane == i) { resA = ra; resB = rb; }
    }
    if (lane < 16) {
        g_max3[(size_t)g0*C3 + ob + lane] = resA;
        g_max3[(size_t)g1*C3 + ob + lane] = resB;
    }
}

// ---------------- finalize: bn2 + relu on pooled maxes ----------------------
__global__ void finalize_kernel(const float* __restrict__ g2,
                                const float* __restrict__ be2,
                                float* __restrict__ out) {
    __shared__ float sc[C3], sh[C3];
    const int tid = threadIdx.x;
    if (tid < C3) {
        const float inv = 1.0f / (float)CNT;
        float m = g_sum2[tid] * inv;
        float v = g_sq2[tid] * inv - m*m;
        float s = g2[tid] * rsqrtf(v + 0.001f);
        sc[tid] = s; sh[tid] = be2[tid] - m*s;
    }
    __syncthreads();
    for (int i = blockIdx.x * blockDim.x + tid; i < B*P*C3; i += gridDim.x * blockDim.x) {
        int o = i & 127;
        out[OFF_NEWPTS + i] = fmaxf(fmaf(g_max3[i], sc[o], sh[o]), 0.f);
    }
}

// ---------------- launch -----------------------------------------------------
extern "C" void kernel_launch(void* const* d_in, const int* in_sizes, int n_in,
                              void* d_out, int out_size) {
    const float* xyz = (const float*)d_in[0];
    const float* pts = (const float*)d_in[1];
    const float* W0  = (const float*)d_in[2];
    const float* g0  = (const float*)d_in[4];
    const float* be0 = (const float*)d_in[5];
    const float* W1  = (const float*)d_in[6];
    const float* g1  = (const float*)d_in[8];
    const float* be1 = (const float*)d_in[9];
    const float* W2  = (const float*)d_in[10];
    const float* g2  = (const float*)d_in[12];
    const float* be2 = (const float*)d_in[13];
    float* out = (float*)d_out;

    const int smemPts = 3 * N * (int)sizeof(float);   // 49152
    cudaFuncSetAttribute(fps_kernel,   cudaFuncAttributeMaxDynamicSharedMemorySize, smemPts);
    cudaFuncSetAttribute(ballq_kernel, cudaFuncAttributeMaxDynamicSharedMemorySize, smemPts);

    zero_stats_kernel<<<1, 128>>>();
    fps_kernel<<<B, FPS_T, smemPts>>>(xyz, out);
    ballq_kernel<<<dim3(P/8, B), 256, smemPts>>>(xyz, out);
    conv1_kernel<<<(B*P)/4, 256>>>(xyz, pts, W0);     // 2 group-pairs / block
    conv2_kernel<<<(B*P)/4, 256>>>(W1, g0, be0);
    conv3_kernel<<<(B*P)/2, 256>>>(W2, g1, be1);      // 1 group-pair / block
    finalize_kernel<<<2048, 256>>>(g2, be2, out);
}

// round 5
// speedup vs baseline: 2.0107x; 1.2027x over previous
#include <cuda_runtime.h>
#include <cuda_bf16.h>
#include <cstdint>

#define B 16
#define N 4096
#define C 64
#define P 1024      // NPOINT
#define S 32        // NSAMPLE
#define CIN0 67
#define C1 64
#define C2 64
#define C3 128
#define CNT (B*P*S) // 524288 samples per channel for BN

#define OFF_NEWXYZ 0
#define OFF_NEWPTS (B*P*3)                 // 49152
#define OFF_IDX    (B*P*3 + B*P*C3)        // 2146304

typedef unsigned long long ull;

// ---------------- f32x2 packed helpers (sm_103a) -----------------------------
__device__ __forceinline__ ull pk2(float x) {
    ull r; asm("mov.b64 %0, {%1, %1};" : "=l"(r) : "f"(x)); return r;
}
__device__ __forceinline__ ull fma2(ull a, ull b, ull c) {
    ull d; asm("fma.rn.f32x2 %0, %1, %2, %3;" : "=l"(d) : "l"(a), "l"(b), "l"(c)); return d;
}
__device__ __forceinline__ ull mul2(ull a, ull b) {
    ull d; asm("mul.rn.f32x2 %0, %1, %2;" : "=l"(d) : "l"(a), "l"(b)); return d;
}
__device__ __forceinline__ ull add2(ull a, ull b) {
    ull d; asm("add.rn.f32x2 %0, %1, %2;" : "=l"(d) : "l"(a), "l"(b)); return d;
}
__device__ __forceinline__ void upk(ull a, float& lo, float& hi) {
    asm("mov.b64 {%0, %1}, %2;" : "=f"(lo), "=f"(hi) : "l"(a));
}
__device__ __forceinline__ ull shfl64(ull v, int off) {
    return __shfl_xor_sync(0xffffffffu, v, off);
}

// ---------------- mma.sync bf16 (baseline sm_80+ PTX, works on sm_103) -------
__device__ __forceinline__ void mma_bf16(float* d, const uint32_t* a, uint32_t b0, uint32_t b1) {
    asm volatile("mma.sync.aligned.m16n8k16.row.col.f32.bf16.bf16.f32 "
        "{%0,%1,%2,%3}, {%4,%5,%6,%7}, {%8,%9}, {%0,%1,%2,%3};"
        : "+f"(d[0]), "+f"(d[1]), "+f"(d[2]), "+f"(d[3])
        : "r"(a[0]), "r"(a[1]), "r"(a[2]), "r"(a[3]), "r"(b0), "r"(b1));
}

// split fp32 pair into bf16x2 (hi) and bf16x2 (residual lo); first arg = low half
__device__ __forceinline__ void split2(float a, float b, uint32_t& hi, uint32_t& lo) {
    __nv_bfloat16 ha = __float2bfloat16_rn(a);
    __nv_bfloat16 hb = __float2bfloat16_rn(b);
    __nv_bfloat162 hh = __halves2bfloat162(ha, hb);
    hi = *reinterpret_cast<uint32_t*>(&hh);
    float la = a - __bfloat162float(ha);
    float lb = b - __bfloat162float(hb);
    __nv_bfloat162 ll = __floats2bfloat162_rn(la, lb);
    lo = *reinterpret_cast<uint32_t*>(&ll);
}

// ---------------- scratch (static device memory; no allocations) ------------
__device__ float g_new_xyz[B*P*3];
__device__ int   g_idx[B*P*S];
// y layout: 16B chunks: [group][chunk 0..15][lane 0..31], chunk = 4 channels
__device__ float g_y1[(size_t)B*P*S*C1];   // 134 MB
__device__ float g_y2[(size_t)B*P*S*C2];   // 134 MB
__device__ float g_max3[(size_t)B*P*C3];   // 8 MB

__device__ float g_sum0[C1], g_sq0[C1];
__device__ float g_sum1[C2], g_sq1[C2];
__device__ float g_sum2[C3], g_sq2[C3];

// ---------------- FPS: one block per batch (also zeroes stats) --------------
#define FPS_T 256
#define FPS_PP (N/FPS_T)   // 16 points per thread
__global__ void fps_kernel(const float* __restrict__ xyz, float* __restrict__ out) {
    extern __shared__ float sm[];
    float* sx = sm; float* sy = sm + N; float* sz = sm + 2*N;
    __shared__ ull skey[2][FPS_T/32];

    const int b = blockIdx.x;
    const int t = threadIdx.x;
    const int lane = t & 31, w = t >> 5;

    if (b == 0) {
        if (t < C1) { g_sum0[t]=0.f; g_sq0[t]=0.f; g_sum1[t]=0.f; g_sq1[t]=0.f; }
        if (t < C3) { g_sum2[t]=0.f; g_sq2[t]=0.f; }
    }

    const float* base = xyz + (size_t)b * N * 3;
    for (int i = t; i < N; i += FPS_T) {
        sx[i] = base[i*3+0]; sy[i] = base[i*3+1]; sz[i] = base[i*3+2];
    }
    __syncthreads();

    float px[FPS_PP], py[FPS_PP], pz[FPS_PP], dd[FPS_PP];
    #pragma unroll
    for (int j = 0; j < FPS_PP; j++) {
        int i = t + j*FPS_T;
        px[j]=sx[i]; py[j]=sy[i]; pz[j]=sz[i]; dd[j]=1e10f;
    }

    int far = 0;
    for (int k = 0; k < P; k++) {
        float fx = sx[far], fy = sy[far], fz = sz[far];
        if (t == 0) {
            size_t gk = (size_t)b*P + k;
            g_new_xyz[gk*3+0]=fx; g_new_xyz[gk*3+1]=fy; g_new_xyz[gk*3+2]=fz;
            out[OFF_NEWXYZ + gk*3+0]=fx; out[OFF_NEWXYZ + gk*3+1]=fy; out[OFF_NEWXYZ + gk*3+2]=fz;
        }
        float bv = -1.f; int bi = 0x7fffffff;
        #pragma unroll
        for (int j = 0; j < FPS_PP; j++) {
            float dx = __fsub_rn(px[j], fx);
            float dy = __fsub_rn(py[j], fy);
            float dz = __fsub_rn(pz[j], fz);
            float d  = __fadd_rn(__fadd_rn(__fmul_rn(dx,dx), __fmul_rn(dy,dy)), __fmul_rn(dz,dz));
            dd[j] = fminf(dd[j], d);
            if (dd[j] > bv) { bv = dd[j]; bi = t + j*FPS_T; }
        }
        unsigned bvb = __float_as_uint(bv);
        unsigned mb  = __reduce_max_sync(0xffffffffu, bvb);
        unsigned bim = (bvb == mb) ? (unsigned)bi : 0x7fffffffu;
        unsigned bmin = __reduce_min_sync(0xffffffffu, bim);
        if (lane == 0) skey[k & 1][w] = ((ull)mb << 32) | (unsigned)(~bmin);
        __syncthreads();
        ull kb = skey[k & 1][0];
        #pragma unroll
        for (int q = 1; q < FPS_T/32; q++) {
            ull o = skey[k & 1][q];
            if (o > kb) kb = o;
        }
        far = (int)(~(unsigned)kb);
    }
}

// ---------------- Ball query: one warp per center ---------------------------
__global__ void ballq_kernel(const float* __restrict__ xyz, float* __restrict__ out) {
    extern __shared__ float sm[];
    float* sx = sm; float* sy = sm + N; float* sz = sm + 2*N;
    const int b = blockIdx.y;
    const int tid = threadIdx.x;
    const float* base = xyz + (size_t)b * N * 3;
    for (int i = tid; i < N; i += blockDim.x) {
        sx[i] = base[i*3+0]; sy[i] = base[i*3+1]; sz[i] = base[i*3+2];
    }
    __syncthreads();

    const int w = tid >> 5, lane = tid & 31;
    const int p = blockIdx.x * 8 + w;
    const int g = b * P + p;
    const float cx = g_new_xyz[g*3+0], cy = g_new_xyz[g*3+1], cz = g_new_xyz[g*3+2];
    const float R2 = (float)(0.4 * 0.4);

    int cnt = 0, first = -1;
    for (int basei = 0; basei < N; basei += 32) {
        int i = basei + lane;
        float dx = __fsub_rn(cx, sx[i]);
        float dy = __fsub_rn(cy, sy[i]);
        float dz = __fsub_rn(cz, sz[i]);
        float d2 = __fadd_rn(__fadd_rn(__fmul_rn(dx,dx), __fmul_rn(dy,dy)), __fmul_rn(dz,dz));
        bool pred = d2 < R2;
        unsigned m = __ballot_sync(0xffffffffu, pred);
        if (first < 0 && m) first = basei + __ffs(m) - 1;
        int rank = cnt + __popc(m & ((1u << lane) - 1u));
        if (pred && rank < S) {
            g_idx[g*S + rank] = i;
            out[OFF_IDX + g*S + rank] = (float)i;
        }
        cnt += __popc(m);
        if (cnt >= S) break;
    }
    int cntc = cnt < S ? cnt : S;
    if (lane >= cntc) {
        g_idx[g*S + lane] = first;
        out[OFF_IDX + g*S + lane] = (float)first;
    }
}

// ---------------- conv1: gather + (67->64), FFMA f32x2 ----------------------
__global__ __launch_bounds__(256, 3) void conv1_kernel(const float* __restrict__ xyz,
                                                       const float* __restrict__ pts,
                                                       const float* __restrict__ W0) {
    __shared__ __align__(16) float Ws[CIN0*C1];           // 17152 B
    const int tid = threadIdx.x;
    for (int i = tid; i < CIN0*C1; i += 256) Ws[i] = W0[i];
    __syncthreads();

    const int w = tid >> 5, lane = tid & 31;
    const int gp = blockIdx.x * 2 + (w >> 2);
    const int quarter = w & 3, ob = quarter * 16;
    const int g0 = gp*2, g1 = gp*2+1;
    const int b = g0 >> 10;

    const int ja = g_idx[g0*S + lane];
    const int jb = g_idx[g1*S + lane];

    const float* xra = xyz + ((size_t)b*N + ja)*3;
    const float* xrb = xyz + ((size_t)b*N + jb)*3;
    float ia[3], ib[3];
    ia[0] = xra[0] - g_new_xyz[g0*3+0]; ia[1] = xra[1] - g_new_xyz[g0*3+1]; ia[2] = xra[2] - g_new_xyz[g0*3+2];
    ib[0] = xrb[0] - g_new_xyz[g1*3+0]; ib[1] = xrb[1] - g_new_xyz[g1*3+1]; ib[2] = xrb[2] - g_new_xyz[g1*3+2];

    ull acca[8], accb[8];
    {
        ull za = pk2(ia[0]), zb = pk2(ib[0]);
        const ulonglong2* wr = (const ulonglong2*)(Ws + 0*C1 + ob);
        #pragma unroll
        for (int p2 = 0; p2 < 4; p2++) {
            ulonglong2 wv = wr[p2];
            acca[2*p2]   = mul2(za, wv.x); acca[2*p2+1] = mul2(za, wv.y);
            accb[2*p2]   = mul2(zb, wv.x); accb[2*p2+1] = mul2(zb, wv.y);
        }
        #pragma unroll
        for (int c = 1; c < 3; c++) {
            ull za2 = pk2(ia[c]), zb2 = pk2(ib[c]);
            const ulonglong2* wr2 = (const ulonglong2*)(Ws + c*C1 + ob);
            #pragma unroll
            for (int p2 = 0; p2 < 4; p2++) {
                ulonglong2 wv = wr2[p2];
                acca[2*p2]   = fma2(za2, wv.x, acca[2*p2]);   acca[2*p2+1] = fma2(za2, wv.y, acca[2*p2+1]);
                accb[2*p2]   = fma2(zb2, wv.x, accb[2*p2]);   accb[2*p2+1] = fma2(zb2, wv.y, accb[2*p2+1]);
            }
        }
    }

    const float4* pra = (const float4*)(pts + ((size_t)b*N + ja)*C);
    const float4* prb = (const float4*)(pts + ((size_t)b*N + jb)*C);
    #pragma unroll 4
    for (int q = 0; q < 16; q++) {
        float4 va = __ldg(pra + q);
        float4 vb = __ldg(prb + q);
        int c = 3 + q*4;
        float fa[4] = {va.x, va.y, va.z, va.w};
        float fb[4] = {vb.x, vb.y, vb.z, vb.w};
        #pragma unroll
        for (int u = 0; u < 4; u++) {
            ull za = pk2(fa[u]), zb = pk2(fb[u]);
            const ulonglong2* wr = (const ulonglong2*)(Ws + (c+u)*C1 + ob);
            #pragma unroll
            for (int p2 = 0; p2 < 4; p2++) {
                ulonglong2 wv = wr[p2];
                acca[2*p2]   = fma2(za, wv.x, acca[2*p2]);   acca[2*p2+1] = fma2(za, wv.y, acca[2*p2+1]);
                accb[2*p2]   = fma2(zb, wv.x, accb[2*p2]);   accb[2*p2+1] = fma2(zb, wv.y, accb[2*p2+1]);
            }
        }
    }

    ulonglong2* yv = (ulonglong2*)g_y1;
    #pragma unroll
    for (int t2 = 0; t2 < 4; t2++) {
        ulonglong2 va, vb;
        va.x = acca[2*t2]; va.y = acca[2*t2+1];
        vb.x = accb[2*t2]; vb.y = accb[2*t2+1];
        yv[((size_t)g0*16 + quarter*4 + t2)*32 + lane] = va;
        yv[((size_t)g1*16 + quarter*4 + t2)*32 + lane] = vb;
    }

    ull ssum = 0, ssq = 0;
    #pragma unroll
    for (int p2 = 0; p2 < 8; p2++) {
        ull s  = add2(acca[p2], accb[p2]);
        ull q2 = add2(mul2(acca[p2], acca[p2]), mul2(accb[p2], accb[p2]));
        #pragma unroll
        for (int off = 16; off > 0; off >>= 1) {
            s  = add2(s,  shfl64(s,  off));
            q2 = add2(q2, shfl64(q2, off));
        }
        if (lane == p2) { ssum = s; ssq = q2; }
    }
    if (lane < 8) {
        float slo, shi, qlo, qhi;
        upk(ssum, slo, shi); upk(ssq, qlo, qhi);
        atomicAdd(&g_sum0[ob + 2*lane],     slo);
        atomicAdd(&g_sum0[ob + 2*lane + 1], shi);
        atomicAdd(&g_sq0[ob + 2*lane],      qlo);
        atomicAdd(&g_sq0[ob + 2*lane + 1],  qhi);
    }
}

// =============================================================================
// conv2: mma.sync bf16 hi/lo split GEMM [32 x 64] @ [64 x 64] per warp/group
// smem layout (bytes): whi @0 (9216), wlo @9216 (9216), zbuf @18432 (4x9216),
//                      params @55296 (ssc64, ssh64, ssum64, ssq64) -> 56320 total
// =============================================================================
#define CV2_WLO   9216
#define CV2_ZB   18432
#define CV2_PAR  55296
#define CV2_SMEM 56320

__global__ __launch_bounds__(128) void conv2_mma(const float* __restrict__ W1,
                                                 const float* __restrict__ g0p,
                                                 const float* __restrict__ be0) {
    extern __shared__ char smraw[];
    uint32_t* whi = (uint32_t*)(smraw);
    uint32_t* wlo = (uint32_t*)(smraw + CV2_WLO);
    float* ssc  = (float*)(smraw + CV2_PAR);
    float* ssh  = ssc + 64;
    float* ssum = ssh + 64;
    float* ssq  = ssum + 64;

    const int tid = threadIdx.x, wid = tid >> 5, lane = tid & 31;
    const int q = lane & 3, r0 = lane >> 2;
    const int g = blockIdx.x * 4 + wid;

    // W pairs: wpair[kk][n] = {W1[2kk][n], W1[2kk+1][n]}, row stride 72 words
    for (int idx = tid; idx < 32*64; idx += 128) {
        int kk = idx >> 6, n = idx & 63;
        uint32_t hi, lo;
        split2(W1[(2*kk)*C2 + n], W1[(2*kk+1)*C2 + n], hi, lo);
        whi[kk*72 + n] = hi; wlo[kk*72 + n] = lo;
    }
    if (tid < 64) {
        const float inv = 1.0f / (float)CNT;
        float m = g_sum0[tid] * inv;
        float v = g_sq0[tid] * inv - m*m;
        float sc = g0p[tid] * rsqrtf(v + 0.001f);
        ssc[tid] = sc; ssh[tid] = be0[tid] - m*sc;
        ssum[tid] = 0.f; ssq[tid] = 0.f;
    }
    __syncthreads();

    uint32_t* zhi = (uint32_t*)(smraw + CV2_ZB) + wid*2304;   // [32][36] words
    uint32_t* zlo = zhi + 1152;

    {   // stage A: lane = sample; BN0 + relu + split
        const float4* xsrc = (const float4*)g_y1 + (size_t)g*512 + lane;
        #pragma unroll
        for (int qq = 0; qq < 16; qq++) {
            float4 v = xsrc[qq*32];
            int c = qq*4;
            float z0 = fmaxf(fmaf(v.x, ssc[c+0], ssh[c+0]), 0.f);
            float z1 = fmaxf(fmaf(v.y, ssc[c+1], ssh[c+1]), 0.f);
            float z2 = fmaxf(fmaf(v.z, ssc[c+2], ssh[c+2]), 0.f);
            float z3 = fmaxf(fmaf(v.w, ssc[c+3], ssh[c+3]), 0.f);
            uint32_t h0, l0, h1, l1;
            split2(z0, z1, h0, l0); split2(z2, z3, h1, l1);
            zhi[lane*36 + 2*qq]     = h0; zhi[lane*36 + 2*qq + 1] = h1;
            zlo[lane*36 + 2*qq]     = l0; zlo[lane*36 + 2*qq + 1] = l1;
        }
    }
    __syncwarp();

    float acc[2][8][4];
    #pragma unroll
    for (int mt = 0; mt < 2; mt++)
        #pragma unroll
        for (int nt = 0; nt < 8; nt++)
            #pragma unroll
            for (int e = 0; e < 4; e++) acc[mt][nt][e] = 0.f;

    #pragma unroll
    for (int ks = 0; ks < 4; ks++) {
        uint32_t ah[2][4], al[2][4];
        const int cb = 8*ks + q;
        #pragma unroll
        for (int mt = 0; mt < 2; mt++) {
            int ra = mt*16 + r0, rb = ra + 8;
            ah[mt][0] = zhi[ra*36 + cb];     ah[mt][1] = zhi[rb*36 + cb];
            ah[mt][2] = zhi[ra*36 + cb + 4]; ah[mt][3] = zhi[rb*36 + cb + 4];
            al[mt][0] = zlo[ra*36 + cb];     al[mt][1] = zlo[rb*36 + cb];
            al[mt][2] = zlo[ra*36 + cb + 4]; al[mt][3] = zlo[rb*36 + cb + 4];
        }
        #pragma unroll
        for (int nt = 0; nt < 8; nt++) {
            int wb  = cb*72 + 8*nt + r0;
            uint32_t bh0 = whi[wb], bh1 = whi[wb + 4*72];
            uint32_t bl0 = wlo[wb], bl1 = wlo[wb + 4*72];
            #pragma unroll
            for (int mt = 0; mt < 2; mt++) {
                mma_bf16(acc[mt][nt], ah[mt], bh0, bh1);
                mma_bf16(acc[mt][nt], ah[mt], bl0, bl1);
                mma_bf16(acc[mt][nt], al[mt], bh0, bh1);
            }
        }
    }
    __syncwarp();

    // D -> smem (overlay z buffers), stride 68 words
    float* Ds = (float*)zhi;
    #pragma unroll
    for (int mt = 0; mt < 2; mt++) {
        int ra = mt*16 + r0;
        #pragma unroll
        for (int nt = 0; nt < 8; nt++) {
            int cbb = 8*nt + 2*q;
            *(float2*)(Ds + ra*68 + cbb)     = make_float2(acc[mt][nt][0], acc[mt][nt][1]);
            *(float2*)(Ds + (ra+8)*68 + cbb) = make_float2(acc[mt][nt][2], acc[mt][nt][3]);
        }
    }
    __syncwarp();

    // y2 store in chunk layout: lane = sample
    float4* ydst = (float4*)g_y2 + (size_t)g*512 + lane;
    #pragma unroll
    for (int qq = 0; qq < 16; qq++)
        ydst[qq*32] = *(float4*)(Ds + lane*68 + 4*qq);

    // column stats: channels lane, lane+32
    #pragma unroll
    for (int cp = 0; cp < 2; cp++) {
        int c = lane + 32*cp;
        float s = 0.f, sq = 0.f;
        #pragma unroll 8
        for (int ss = 0; ss < 32; ss++) {
            float x = Ds[ss*68 + c];
            s += x; sq += x*x;
        }
        atomicAdd(&ssum[c], s);
        atomicAdd(&ssq[c],  sq);
    }
    __syncthreads();
    if (tid < 64) {
        atomicAdd(&g_sum1[tid], ssum[tid]);
        atomicAdd(&g_sq1[tid],  ssq[tid]);
    }
}

// =============================================================================
// conv3: mma.sync bf16 GEMM [32 x 64] @ [64 x 128] + stats + max-pool
// smem: whi @0 (17408), wlo @17408 (17408), zbuf @34816 (4x9216),
//       params @71680 (ssc64, ssh64, ssum128, ssq128 = 1536) -> 73216 total
// =============================================================================
#define CV3_WLO  17408
#define CV3_ZB   34816
#define CV3_PAR  71680
#define CV3_SMEM 73216

__global__ __launch_bounds__(128) void conv3_mma(const float* __restrict__ W2,
                                                 const float* __restrict__ g1p,
                                                 const float* __restrict__ be1) {
    extern __shared__ char smraw[];
    uint32_t* whi = (uint32_t*)(smraw);
    uint32_t* wlo = (uint32_t*)(smraw + CV3_WLO);
    float* ssc   = (float*)(smraw + CV3_PAR);
    float* ssh   = ssc + 64;
    float* ssum2 = ssh + 64;    // [128]
    float* ssq2  = ssum2 + 128; // [128]

    const int tid = threadIdx.x, wid = tid >> 5, lane = tid & 31;
    const int q = lane & 3, r0 = lane >> 2;
    const int g = blockIdx.x * 4 + wid;

    // W pairs: wpair[kk][n] = {W2[2kk][n], W2[2kk+1][n]}, row stride 136 words
    for (int idx = tid; idx < 32*128; idx += 128) {
        int kk = idx >> 7, n = idx & 127;
        uint32_t hi, lo;
        split2(W2[(2*kk)*C3 + n], W2[(2*kk+1)*C3 + n], hi, lo);
        whi[kk*136 + n] = hi; wlo[kk*136 + n] = lo;
    }
    if (tid < 64) {
        const float inv = 1.0f / (float)CNT;
        float m = g_sum1[tid] * inv;
        float v = g_sq1[tid] * inv - m*m;
        float sc = g1p[tid] * rsqrtf(v + 0.001f);
        ssc[tid] = sc; ssh[tid] = be1[tid] - m*sc;
    }
    ssum2[tid] = 0.f; ssq2[tid] = 0.f;
    __syncthreads();

    uint32_t* zhi = (uint32_t*)(smraw + CV3_ZB) + wid*2304;
    uint32_t* zlo = zhi + 1152;

    {   // stage A: BN1 + relu + split from y2
        const float4* xsrc = (const float4*)g_y2 + (size_t)g*512 + lane;
        #pragma unroll
        for (int qq = 0; qq < 16; qq++) {
            float4 v = xsrc[qq*32];
            int c = qq*4;
            float z0 = fmaxf(fmaf(v.x, ssc[c+0], ssh[c+0]), 0.f);
            float z1 = fmaxf(fmaf(v.y, ssc[c+1], ssh[c+1]), 0.f);
            float z2 = fmaxf(fmaf(v.z, ssc[c+2], ssh[c+2]), 0.f);
            float z3 = fmaxf(fmaf(v.w, ssc[c+3], ssh[c+3]), 0.f);
            uint32_t h0, l0, h1, l1;
            split2(z0, z1, h0, l0); split2(z2, z3, h1, l1);
            zhi[lane*36 + 2*qq]     = h0; zhi[lane*36 + 2*qq + 1] = h1;
            zlo[lane*36 + 2*qq]     = l0; zlo[lane*36 + 2*qq + 1] = l1;
        }
    }
    __syncwarp();

    #pragma unroll 1
    for (int ch = 0; ch < 4; ch++) {       // 4 n-chunks of 32 cols
        float acc[2][4][4];
        #pragma unroll
        for (int mt = 0; mt < 2; mt++)
            #pragma unroll
            for (int ntl = 0; ntl < 4; ntl++)
                #pragma unroll
                for (int e = 0; e < 4; e++) acc[mt][ntl][e] = 0.f;

        #pragma unroll
        for (int ks = 0; ks < 4; ks++) {
            uint32_t ah[2][4], al[2][4];
            const int cb = 8*ks + q;
            #pragma unroll
            for (int mt = 0; mt < 2; mt++) {
                int ra = mt*16 + r0, rb = ra + 8;
                ah[mt][0] = zhi[ra*36 + cb];     ah[mt][1] = zhi[rb*36 + cb];
                ah[mt][2] = zhi[ra*36 + cb + 4]; ah[mt][3] = zhi[rb*36 + cb + 4];
                al[mt][0] = zlo[ra*36 + cb];     al[mt][1] = zlo[rb*36 + cb];
                al[mt][2] = zlo[ra*36 + cb + 4]; al[mt][3] = zlo[rb*36 + cb + 4];
            }
            #pragma unroll
            for (int ntl = 0; ntl < 4; ntl++) {
                int nt = ch*4 + ntl;
                int wb = cb*136 + 8*nt + r0;
                uint32_t bh0 = whi[wb], bh1 = whi[wb + 4*136];
                uint32_t bl0 = wlo[wb], bl1 = wlo[wb + 4*136];
                #pragma unroll
                for (int mt = 0; mt < 2; mt++) {
                    mma_bf16(acc[mt][ntl], ah[mt], bh0, bh1);
                    mma_bf16(acc[mt][ntl], ah[mt], bl0, bl1);
                    mma_bf16(acc[mt][ntl], al[mt], bh0, bh1);
                }
            }
        }

        // fragment-space reduction: per thread cols c0=8nt+2q, c1=c0+1
        #pragma unroll
        for (int ntl = 0; ntl < 4; ntl++) {
            int nt = ch*4 + ntl;
            float v00 = acc[0][ntl][0], v02 = acc[0][ntl][2];
            float v10 = acc[1][ntl][0], v12 = acc[1][ntl][2];
            float v01 = acc[0][ntl][1], v03 = acc[0][ntl][3];
            float v11 = acc[1][ntl][1], v13 = acc[1][ntl][3];
            float s0 = v00 + v02 + v10 + v12;
            float s1 = v01 + v03 + v11 + v13;
            float q0 = v00*v00 + v02*v02 + v10*v10 + v12*v12;
            float q1 = v01*v01 + v03*v03 + v11*v11 + v13*v13;
            float m0 = fmaxf(fmaxf(v00, v02), fmaxf(v10, v12));
            float m1 = fmaxf(fmaxf(v01, v03), fmaxf(v11, v13));
            #pragma unroll
            for (int off = 4; off < 32; off <<= 1) {
                s0 += __shfl_xor_sync(0xffffffffu, s0, off);
                s1 += __shfl_xor_sync(0xffffffffu, s1, off);
                q0 += __shfl_xor_sync(0xffffffffu, q0, off);
                q1 += __shfl_xor_sync(0xffffffffu, q1, off);
                m0 = fmaxf(m0, __shfl_xor_sync(0xffffffffu, m0, off));
                m1 = fmaxf(m1, __shfl_xor_sync(0xffffffffu, m1, off));
            }
            if (r0 == 0) {   // lanes 0..3
                int c = 8*nt + 2*q;
                atomicAdd(&ssum2[c],   s0); atomicAdd(&ssum2[c+1], s1);
                atomicAdd(&ssq2[c],    q0); atomicAdd(&ssq2[c+1],  q1);
                g_max3[(size_t)g*C3 + c]     = m0;
                g_max3[(size_t)g*C3 + c + 1] = m1;
            }
        }
    }
    __syncthreads();
    atomicAdd(&g_sum2[tid], ssum2[tid]);
    atomicAdd(&g_sq2[tid],  ssq2[tid]);
}

// ---------------- finalize: bn2 + relu on pooled maxes ----------------------
__global__ void finalize_kernel(const float* __restrict__ g2,
                                const float* __restrict__ be2,
                                float* __restrict__ out) {
    __shared__ float sc[C3], sh[C3];
    const int tid = threadIdx.x;
    if (tid < C3) {
        const float inv = 1.0f / (float)CNT;
        float m = g_sum2[tid] * inv;
        float v = g_sq2[tid] * inv - m*m;
        float s = g2[tid] * rsqrtf(v + 0.001f);
        sc[tid] = s; sh[tid] = be2[tid] - m*s;
    }
    __syncthreads();
    for (int i = blockIdx.x * blockDim.x + tid; i < B*P*C3; i += gridDim.x * blockDim.x) {
        int o = i & 127;
        out[OFF_NEWPTS + i] = fmaxf(fmaf(g_max3[i], sc[o], sh[o]), 0.f);
    }
}

// ---------------- launch -----------------------------------------------------
extern "C" void kernel_launch(void* const* d_in, const int* in_sizes, int n_in,
                              void* d_out, int out_size) {
    const float* xyz = (const float*)d_in[0];
    const float* pts = (const float*)d_in[1];
    const float* W0  = (const float*)d_in[2];
    const float* g0  = (const float*)d_in[4];
    const float* be0 = (const float*)d_in[5];
    const float* W1  = (const float*)d_in[6];
    const float* g1  = (const float*)d_in[8];
    const float* be1 = (const float*)d_in[9];
    const float* W2  = (const float*)d_in[10];
    const float* g2  = (const float*)d_in[12];
    const float* be2 = (const float*)d_in[13];
    float* out = (float*)d_out;

    const int smemPts = 3 * N * (int)sizeof(float);   // 49152
    cudaFuncSetAttribute(fps_kernel,   cudaFuncAttributeMaxDynamicSharedMemorySize, smemPts);
    cudaFuncSetAttribute(ballq_kernel, cudaFuncAttributeMaxDynamicSharedMemorySize, smemPts);
    cudaFuncSetAttribute(conv2_mma, cudaFuncAttributeMaxDynamicSharedMemorySize, CV2_SMEM);
    cudaFuncSetAttribute(conv3_mma, cudaFuncAttributeMaxDynamicSharedMemorySize, CV3_SMEM);

    fps_kernel<<<B, FPS_T, smemPts>>>(xyz, out);
    ballq_kernel<<<dim3(P/8, B), 256, smemPts>>>(xyz, out);
    conv1_kernel<<<(B*P)/4, 256>>>(xyz, pts, W0);
    conv2_mma<<<(B*P)/4, 128, CV2_SMEM>>>(W1, g0, be0);
    conv3_mma<<<(B*P)/4, 128, CV3_SMEM>>>(W2, g1, be1);
    finalize_kernel<<<2048, 256>>>(g2, be2, out);
}